// round 2
// baseline (speedup 1.0000x reference)
#include <cuda_runtime.h>

#define N_NODES 200000
#define E_TP    200000
#define E_IT    3200000

// -------- scratch (static device globals; no allocation) --------
__device__ int   g_cnt_tp[N_NODES];
__device__ int   g_cnt_it[N_NODES];
__device__ int   g_off_tp[N_NODES + 1];
__device__ int   g_off_it[N_NODES + 1];
__device__ int   g_src_tp[E_TP];
__device__ int   g_src_it[E_IT];
__device__ float g_h0[N_NODES * 32];
__device__ float g_h1[N_NODES * 32];

// -------- CSR build --------
__global__ void zero_cnt_kernel() {
    int i = blockIdx.x * blockDim.x + threadIdx.x;
    if (i < N_NODES) { g_cnt_tp[i] = 0; g_cnt_it[i] = 0; }
}

__global__ void hist_kernel(const int* __restrict__ ei_tp,
                            const int* __restrict__ ei_it) {
    int e = blockIdx.x * blockDim.x + threadIdx.x;
    if (e < E_TP) atomicAdd(&g_cnt_tp[ei_tp[E_TP + e]], 1);
    if (e < E_IT) atomicAdd(&g_cnt_it[ei_it[E_IT + e]], 1);
}

// single-block exclusive scan over N_NODES counts (which: 0=tp, 1=it)
__global__ void scan_kernel(int which) {
    const int* cnt = which ? g_cnt_it : g_cnt_tp;
    int*       off = which ? g_off_it : g_off_tp;
    const int n = N_NODES;
    __shared__ int s_sum[1024];
    int t = threadIdx.x;
    int chunk = (n + 1023) >> 10;
    int begin = min(t * chunk, n);
    int end   = min(begin + chunk, n);
    int sum = 0;
    for (int i = begin; i < end; i++) sum += cnt[i];
    s_sum[t] = sum;
    __syncthreads();
    for (int d = 1; d < 1024; d <<= 1) {
        int v = (t >= d) ? s_sum[t - d] : 0;
        __syncthreads();
        s_sum[t] += v;
        __syncthreads();
    }
    int run = (t == 0) ? 0 : s_sum[t - 1];
    for (int i = begin; i < end; i++) { off[i] = run; run += cnt[i]; }
    if (t == 0) off[n] = s_sum[1023];
}

__global__ void scatter_kernel(const int* __restrict__ ei_tp,
                               const int* __restrict__ ei_it) {
    int e = blockIdx.x * blockDim.x + threadIdx.x;
    if (e < E_TP) {
        int src = ei_tp[e];
        int dst = ei_tp[E_TP + e];
        int pos = g_off_tp[dst] + atomicAdd(&g_cnt_tp[dst], 1);
        g_src_tp[pos] = src;
    }
    if (e < E_IT) {
        int src = ei_it[e];
        int dst = ei_it[E_IT + e];
        int pos = g_off_it[dst] + atomicAdd(&g_cnt_it[dst], 1);
        g_src_it[pos] = src;
    }
}

// -------- fused hetero-conv layer --------
// One warp per node; lane = channel. IO: 0 = xin->g_h0, 1 = g_h0->g_h1, 2 = g_h1->g_h0.
template <int CIN, bool RES, int IO>
__global__ void __launch_bounds__(256)
conv_kernel(const float* __restrict__ xin,
            const float* __restrict__ Wa,  const float* __restrict__ Wm,
            const float* __restrict__ Wr0, const float* __restrict__ Wr1,
            const float* __restrict__ b0,  const float* __restrict__ b1) {
    __shared__ __align__(16) float s_wa[CIN * 32];
    __shared__ __align__(16) float s_wm[CIN * 32];
    __shared__ __align__(16) float s_wr[CIN * 32];
    __shared__ __align__(16) float s_b[32];

    const float* hin  = (IO == 0) ? xin : (IO == 1 ? g_h0 : g_h1);
    float*       hout = (IO == 1) ? g_h1 : g_h0;

    int t = threadIdx.x;
    for (int i = t; i < CIN * 32; i += blockDim.x) {
        s_wa[i] = Wa[i];
        s_wm[i] = Wm[i];
        s_wr[i] = Wr0[i] + Wr1[i];
    }
    if (t < 32) s_b[t] = b0[t] + b1[t];
    __syncthreads();

    int lane = t & 31;
    int node = blockIdx.x * (blockDim.x >> 5) + (t >> 5);
    if (node >= N_NODES) return;

    float X = 0.f;
    if (CIN == 32) X = hin[node * 32 + lane];
    else if (lane < CIN) X = hin[node * CIN + lane];

    // add-aggregation over temp_previous
    float A0 = 0.f, A1 = 0.f;
    int beg = g_off_tp[node], end = g_off_tp[node + 1];
    for (int j = beg; j < end; j += 32) {
        int s = (j + lane < end) ? g_src_tp[j + lane] : -1;
#pragma unroll
        for (int k = 0; k < 32; k += 2) {
            int s0 = __shfl_sync(0xffffffffu, s, k);
            int s1 = __shfl_sync(0xffffffffu, s, k + 1);
            if (s0 >= 0 && (CIN == 32 || lane < CIN)) A0 += hin[s0 * CIN + lane];
            if (s1 >= 0 && (CIN == 32 || lane < CIN)) A1 += hin[s1 * CIN + lane];
        }
    }
    float A = A0 + A1;

    // mean-aggregation over intersects
    float M0 = 0.f, M1 = 0.f;
    beg = g_off_it[node]; end = g_off_it[node + 1];
    int cnt = end - beg;
    for (int j = beg; j < end; j += 32) {
        int s = (j + lane < end) ? g_src_it[j + lane] : -1;
#pragma unroll
        for (int k = 0; k < 32; k += 2) {
            int s0 = __shfl_sync(0xffffffffu, s, k);
            int s1 = __shfl_sync(0xffffffffu, s, k + 1);
            if (s0 >= 0 && (CIN == 32 || lane < CIN)) M0 += hin[s0 * CIN + lane];
            if (s1 >= 0 && (CIN == 32 || lane < CIN)) M1 += hin[s1 * CIN + lane];
        }
    }
    float M = (M0 + M1) / fmaxf((float)cnt, 1.0f);

    // out = A@Wa + M@Wm + X@(Wr0+Wr1) + (b0+b1)  via shuffle broadcast
    float out = s_b[lane];
#pragma unroll
    for (int c = 0; c < CIN; c++) {
        float av = __shfl_sync(0xffffffffu, A, c);
        float mv = __shfl_sync(0xffffffffu, M, c);
        float xv = __shfl_sync(0xffffffffu, X, c);
        out += av * s_wa[c * 32 + lane];
        out += mv * s_wm[c * 32 + lane];
        out += xv * s_wr[c * 32 + lane];
    }
    if (RES) out += X;
    out = fmaxf(out, 0.f);
    hout[node * 32 + lane] = out;
}

// -------- final linear 32 -> 128 --------
__global__ void __launch_bounds__(256)
out_kernel(float* __restrict__ out,
           const float* __restrict__ Wout, const float* __restrict__ bout) {
    __shared__ __align__(16) float s_w[32 * 128];
    __shared__ __align__(16) float s_b[128];
    int t = threadIdx.x;
    for (int i = t; i < 32 * 128; i += blockDim.x) s_w[i] = Wout[i];
    if (t < 128) s_b[t] = bout[t];
    __syncthreads();

    int lane = t & 31;
    int node = blockIdx.x * (blockDim.x >> 5) + (t >> 5);
    if (node >= N_NODES) return;

    float h = g_h0[node * 32 + lane];
    float4 acc = *(const float4*)&s_b[lane * 4];
#pragma unroll
    for (int c = 0; c < 32; c++) {
        float hv = __shfl_sync(0xffffffffu, h, c);
        float4 w = *(const float4*)&s_w[c * 128 + lane * 4];
        acc.x += hv * w.x; acc.y += hv * w.y;
        acc.z += hv * w.z; acc.w += hv * w.w;
    }
    *(float4*)&out[node * 128 + lane * 4] = acc;
}

extern "C" void kernel_launch(void* const* d_in, const int* in_sizes, int n_in,
                              void* d_out, int out_size) {
    const float* x       = (const float*)d_in[0];
    const int*   ei_tp   = (const int*)d_in[1];    // (2, E_TP) int32
    const int*   ei_it   = (const int*)d_in[2];    // (2, E_IT) int32
    const float* W0_rel  = (const float*)d_in[3];  // (2,6,32)
    const float* W0_root = (const float*)d_in[4];  // (2,6,32)
    const float* b0      = (const float*)d_in[5];  // (2,32)
    const float* W_rel   = (const float*)d_in[6];  // (4,2,32,32)
    const float* W_root  = (const float*)d_in[7];  // (4,2,32,32)
    const float* b       = (const float*)d_in[8];  // (4,2,32)
    const float* Wout    = (const float*)d_in[9];  // (32,128)
    const float* bout    = (const float*)d_in[10]; // (128,)
    float*       out     = (float*)d_out;

    int gz = (N_NODES + 255) / 256;
    int ge = (E_IT + 255) / 256;
    zero_cnt_kernel<<<gz, 256>>>();
    hist_kernel<<<ge, 256>>>(ei_tp, ei_it);
    scan_kernel<<<1, 1024>>>(0);
    scan_kernel<<<1, 1024>>>(1);
    zero_cnt_kernel<<<gz, 256>>>();
    scatter_kernel<<<ge, 256>>>(ei_tp, ei_it);

    int gn = (N_NODES + 7) / 8;  // 8 warps (nodes) per 256-thread block

    // head: 6 -> 32, no residual, x -> g_h0
    conv_kernel<6, false, 0><<<gn, 256>>>(x,
        W0_rel, W0_rel + 6 * 32, W0_root, W0_root + 6 * 32, b0, b0 + 32);

    // 4 residual blocks, ping-pong g_h0 <-> g_h1
    for (int i = 0; i < 4; i++) {
        const float* wr  = W_rel  + i * 2048;
        const float* wro = W_root + i * 2048;
        const float* bb  = b      + i * 64;
        if ((i & 1) == 0)
            conv_kernel<32, true, 1><<<gn, 256>>>(nullptr, wr, wr + 1024,
                                                  wro, wro + 1024, bb, bb + 32);
        else
            conv_kernel<32, true, 2><<<gn, 256>>>(nullptr, wr, wr + 1024,
                                                  wro, wro + 1024, bb, bb + 32);
    }
    // after head->h0, blocks: h0->h1->h0->h1->h0 ; final in g_h0
    out_kernel<<<gn, 256>>>(out, Wout, bout);
}

// round 5
// speedup vs baseline: 1.5496x; 1.5496x over previous
#include <cuda_runtime.h>

#define N_NODES 200000
#define E_TP    200000
#define E_IT    3200000
#define NB      ((N_NODES + 1023) / 1024)   // 196 scan blocks

// -------- scratch (static device globals; no allocation) --------
__device__ int   g_cnt_tp[N_NODES];
__device__ int   g_cnt_it[N_NODES];
__device__ int   g_off_tp[N_NODES + 1];
__device__ int   g_off_it[N_NODES + 1];
__device__ int   g_src_tp[E_TP];
__device__ int   g_src_it[E_IT];
__device__ int   g_bsum[2 * 256];
__device__ int   g_boff[2 * 256];
__device__ float g_h0[N_NODES * 32];
__device__ float g_h1[N_NODES * 32];

// -------- CSR build --------
__global__ void zero_cnt_kernel() {
    int i = blockIdx.x * blockDim.x + threadIdx.x;
    if (i < N_NODES) { g_cnt_tp[i] = 0; g_cnt_it[i] = 0; }
}

__global__ void hist_kernel(const int* __restrict__ ei_tp,
                            const int* __restrict__ ei_it) {
    int e = blockIdx.x * blockDim.x + threadIdx.x;
    if (e < E_TP) atomicAdd(&g_cnt_tp[ei_tp[E_TP + e]], 1);
    if (e < E_IT) atomicAdd(&g_cnt_it[ei_it[E_IT + e]], 1);
}

// pass 1: per-block sums (1024 elems/block) for both count arrays
__global__ void __launch_bounds__(1024) scan1_kernel() {
    int b = blockIdx.x, t = threadIdx.x;
    int i = b * 1024 + t;
    int vtp = (i < N_NODES) ? g_cnt_tp[i] : 0;
    int vit = (i < N_NODES) ? g_cnt_it[i] : 0;
#pragma unroll
    for (int o = 16; o; o >>= 1) {
        vtp += __shfl_down_sync(0xffffffffu, vtp, o);
        vit += __shfl_down_sync(0xffffffffu, vit, o);
    }
    __shared__ int stp[32], sit[32];
    if ((t & 31) == 0) { stp[t >> 5] = vtp; sit[t >> 5] = vit; }
    __syncthreads();
    if (t < 32) {
        int a = stp[t], c = sit[t];
#pragma unroll
        for (int o = 16; o; o >>= 1) {
            a += __shfl_down_sync(0xffffffffu, a, o);
            c += __shfl_down_sync(0xffffffffu, c, o);
        }
        if (t == 0) { g_bsum[b] = a; g_bsum[256 + b] = c; }
    }
}

// pass 2: tiny serial scan over 196 block sums (x2)
__global__ void scan2_kernel() {
    if (threadIdx.x == 0) {
        int run = 0;
        for (int b = 0; b < NB; b++) { g_boff[b] = run; run += g_bsum[b]; }
        run = 0;
        for (int b = 0; b < NB; b++) { g_boff[256 + b] = run; run += g_bsum[256 + b]; }
        g_off_tp[N_NODES] = E_TP;
        g_off_it[N_NODES] = E_IT;
    }
}

// pass 3: block-local exclusive scan + block offset, for both arrays
__global__ void __launch_bounds__(1024) scan3_kernel() {
    __shared__ int s[1024];
    int b = blockIdx.x, t = threadIdx.x;
    int i = b * 1024 + t;

    // temp_previous
    int v = (i < N_NODES) ? g_cnt_tp[i] : 0;
    s[t] = v;
    __syncthreads();
    for (int d = 1; d < 1024; d <<= 1) {
        int w = (t >= d) ? s[t - d] : 0;
        __syncthreads();
        s[t] += w;
        __syncthreads();
    }
    if (i < N_NODES) g_off_tp[i] = g_boff[b] + s[t] - v;
    __syncthreads();

    // intersects
    v = (i < N_NODES) ? g_cnt_it[i] : 0;
    s[t] = v;
    __syncthreads();
    for (int d = 1; d < 1024; d <<= 1) {
        int w = (t >= d) ? s[t - d] : 0;
        __syncthreads();
        s[t] += w;
        __syncthreads();
    }
    if (i < N_NODES) g_off_it[i] = g_boff[256 + b] + s[t] - v;
}

__global__ void scatter_kernel(const int* __restrict__ ei_tp,
                               const int* __restrict__ ei_it) {
    int e = blockIdx.x * blockDim.x + threadIdx.x;
    if (e < E_TP) {
        int src = ei_tp[e];
        int dst = ei_tp[E_TP + e];
        int pos = g_off_tp[dst] + atomicAdd(&g_cnt_tp[dst], 1);
        g_src_tp[pos] = src;
    }
    if (e < E_IT) {
        int src = ei_it[e];
        int dst = ei_it[E_IT + e];
        int pos = g_off_it[dst] + atomicAdd(&g_cnt_it[dst], 1);
        g_src_it[pos] = src;
    }
}

// -------- fused hetero-conv layer --------
// One warp per node; lane = channel. IO: 0 = xin->g_h0, 1 = g_h0->g_h1, 2 = g_h1->g_h0.
template <int CIN, bool RES, int IO>
__global__ void __launch_bounds__(256)
conv_kernel(const float* __restrict__ xin,
            const float* __restrict__ Wa,  const float* __restrict__ Wm,
            const float* __restrict__ Wr0, const float* __restrict__ Wr1,
            const float* __restrict__ b0,  const float* __restrict__ b1) {
    __shared__ __align__(16) float s_wa[CIN * 32];
    __shared__ __align__(16) float s_wm[CIN * 32];
    __shared__ __align__(16) float s_wr[CIN * 32];
    __shared__ __align__(16) float s_b[32];

    const float* hin  = (IO == 0) ? xin : (IO == 1 ? g_h0 : g_h1);
    float*       hout = (IO == 1) ? g_h1 : g_h0;

    int t = threadIdx.x;
    for (int i = t; i < CIN * 32; i += blockDim.x) {
        s_wa[i] = Wa[i];
        s_wm[i] = Wm[i];
        s_wr[i] = Wr0[i] + Wr1[i];
    }
    if (t < 32) s_b[t] = b0[t] + b1[t];
    __syncthreads();

    int lane = t & 31;
    int node = blockIdx.x * (blockDim.x >> 5) + (t >> 5);
    if (node >= N_NODES) return;

    const bool ok = (CIN == 32) || (lane < CIN);

    float X = 0.f;
    if (ok) X = hin[node * CIN + lane];

    // ---- add-aggregation over temp_previous ----
    float A0 = 0.f, A1 = 0.f, A2 = 0.f, A3 = 0.f;
    {
        int beg = g_off_tp[node], end = g_off_tp[node + 1];
        for (int j = beg; j < end; ) {
            int s = (j + lane < end) ? g_src_tp[j + lane] : 0;
            int rem = min(32, end - j);
            int k = 0;
            for (; k + 4 <= rem; k += 4) {
                int s0 = __shfl_sync(0xffffffffu, s, k);
                int s1 = __shfl_sync(0xffffffffu, s, k + 1);
                int s2 = __shfl_sync(0xffffffffu, s, k + 2);
                int s3 = __shfl_sync(0xffffffffu, s, k + 3);
                if (ok) {
                    A0 += hin[s0 * CIN + lane];
                    A1 += hin[s1 * CIN + lane];
                    A2 += hin[s2 * CIN + lane];
                    A3 += hin[s3 * CIN + lane];
                }
            }
            for (; k < rem; k++) {
                int sk = __shfl_sync(0xffffffffu, s, k);
                if (ok) A0 += hin[sk * CIN + lane];
            }
            j += rem;
        }
    }
    float A = (A0 + A1) + (A2 + A3);

    // ---- mean-aggregation over intersects ----
    float M0 = 0.f, M1 = 0.f, M2 = 0.f, M3 = 0.f;
    int beg = g_off_it[node], end = g_off_it[node + 1];
    int cnt = end - beg;
    for (int j = beg; j < end; ) {
        int s = (j + lane < end) ? g_src_it[j + lane] : 0;
        int rem = min(32, end - j);
        int k = 0;
        for (; k + 4 <= rem; k += 4) {
            int s0 = __shfl_sync(0xffffffffu, s, k);
            int s1 = __shfl_sync(0xffffffffu, s, k + 1);
            int s2 = __shfl_sync(0xffffffffu, s, k + 2);
            int s3 = __shfl_sync(0xffffffffu, s, k + 3);
            if (ok) {
                M0 += hin[s0 * CIN + lane];
                M1 += hin[s1 * CIN + lane];
                M2 += hin[s2 * CIN + lane];
                M3 += hin[s3 * CIN + lane];
            }
        }
        for (; k < rem; k++) {
            int sk = __shfl_sync(0xffffffffu, s, k);
            if (ok) M0 += hin[sk * CIN + lane];
        }
        j += rem;
    }
    float M = ((M0 + M1) + (M2 + M3)) / fmaxf((float)cnt, 1.0f);

    // out = A@Wa + M@Wm + X@(Wr0+Wr1) + (b0+b1)  via shuffle broadcast
    float out = s_b[lane];
#pragma unroll
    for (int c = 0; c < CIN; c++) {
        float av = __shfl_sync(0xffffffffu, A, c);
        float mv = __shfl_sync(0xffffffffu, M, c);
        float xv = __shfl_sync(0xffffffffu, X, c);
        out += av * s_wa[c * 32 + lane];
        out += mv * s_wm[c * 32 + lane];
        out += xv * s_wr[c * 32 + lane];
    }
    if (RES) out += X;
    out = fmaxf(out, 0.f);
    hout[node * 32 + lane] = out;
}

// -------- final linear 32 -> 128 --------
__global__ void __launch_bounds__(256)
out_kernel(float* __restrict__ out,
           const float* __restrict__ Wout, const float* __restrict__ bout) {
    __shared__ __align__(16) float s_w[32 * 128];
    __shared__ __align__(16) float s_b[128];
    int t = threadIdx.x;
    for (int i = t; i < 32 * 128; i += blockDim.x) s_w[i] = Wout[i];
    if (t < 128) s_b[t] = bout[t];
    __syncthreads();

    int lane = t & 31;
    int node = blockIdx.x * (blockDim.x >> 5) + (t >> 5);
    if (node >= N_NODES) return;

    float h = g_h0[node * 32 + lane];
    float4 acc = *(const float4*)&s_b[lane * 4];
#pragma unroll
    for (int c = 0; c < 32; c++) {
        float hv = __shfl_sync(0xffffffffu, h, c);
        float4 w = *(const float4*)&s_w[c * 128 + lane * 4];
        acc.x += hv * w.x; acc.y += hv * w.y;
        acc.z += hv * w.z; acc.w += hv * w.w;
    }
    *(float4*)&out[node * 128 + lane * 4] = acc;
}

extern "C" void kernel_launch(void* const* d_in, const int* in_sizes, int n_in,
                              void* d_out, int out_size) {
    const float* x       = (const float*)d_in[0];
    const int*   ei_tp   = (const int*)d_in[1];    // (2, E_TP) int32
    const int*   ei_it   = (const int*)d_in[2];    // (2, E_IT) int32
    const float* W0_rel  = (const float*)d_in[3];  // (2,6,32)
    const float* W0_root = (const float*)d_in[4];  // (2,6,32)
    const float* b0      = (const float*)d_in[5];  // (2,32)
    const float* W_rel   = (const float*)d_in[6];  // (4,2,32,32)
    const float* W_root  = (const float*)d_in[7];  // (4,2,32,32)
    const float* b       = (const float*)d_in[8];  // (4,2,32)
    const float* Wout    = (const float*)d_in[9];  // (32,128)
    const float* bout    = (const float*)d_in[10]; // (128,)
    float*       out     = (float*)d_out;

    int gz = (N_NODES + 255) / 256;
    int ge = (E_IT + 255) / 256;
    zero_cnt_kernel<<<gz, 256>>>();
    hist_kernel<<<ge, 256>>>(ei_tp, ei_it);
    scan1_kernel<<<NB, 1024>>>();
    scan2_kernel<<<1, 32>>>();
    scan3_kernel<<<NB, 1024>>>();
    zero_cnt_kernel<<<gz, 256>>>();
    scatter_kernel<<<ge, 256>>>(ei_tp, ei_it);

    int gn = (N_NODES + 7) / 8;  // 8 warps (nodes) per 256-thread block

    // head: 6 -> 32, no residual, x -> g_h0
    conv_kernel<6, false, 0><<<gn, 256>>>(x,
        W0_rel, W0_rel + 6 * 32, W0_root, W0_root + 6 * 32, b0, b0 + 32);

    // 4 residual blocks, ping-pong g_h0 <-> g_h1
    for (int i = 0; i < 4; i++) {
        const float* wr  = W_rel  + i * 2048;
        const float* wro = W_root + i * 2048;
        const float* bb  = b      + i * 64;
        if ((i & 1) == 0)
            conv_kernel<32, true, 1><<<gn, 256>>>(nullptr, wr, wr + 1024,
                                                  wro, wro + 1024, bb, bb + 32);
        else
            conv_kernel<32, true, 2><<<gn, 256>>>(nullptr, wr, wr + 1024,
                                                  wro, wro + 1024, bb, bb + 32);
    }
    // after head->h0, blocks: h0->h1->h0->h1->h0 ; final in g_h0
    out_kernel<<<gn, 256>>>(out, Wout, bout);
}